// round 1
// baseline (speedup 1.0000x reference)
#include <cuda_runtime.h>
#include <cuda_bf16.h>
#include <cstdint>

#define D      768
#define NTOK   16384          // 8 * 2048
#define SPLIT  8
#define KSPLIT (NTOK / SPLIT) // 2048
#define KT     32
#define KPAD   40
#define NIT    (KSPLIT / KT)  // 64
#define NTILE  6              // 768 / 128
#define NBLK   (NTOK / 64)    // 256

// Scratch (allocation-free rule: __device__ globals)
__device__ __nv_bfloat16 g_Xt[(size_t)D * NTOK];        // X transposed, bf16  (25.2 MB)
__device__ float         g_part[(size_t)SPLIT * D * D]; // split-K partials    (18.9 MB)
__device__ float         g_colsq[(size_t)NBLK * D];     // fp32 sum(x^2) partials

// ---------------------------------------------------------------------------
// Kernel 1: fp32 [N,768] -> bf16 transposed [768,N], fused fp32 column sum-sq
// ---------------------------------------------------------------------------
__global__ __launch_bounds__(256) void convert_kernel(const float* __restrict__ x) {
    __shared__ float tile[64][65];
    const int n0 = blockIdx.x * 64;
    const int c0 = blockIdx.y * 64;
    const int t  = threadIdx.x;

    // Load 64x64 fp32 tile, coalesced along columns
    const int fr = t >> 4;   // 0..15
    const int fc = t & 15;   // float4 index in row
    #pragma unroll
    for (int rr = 0; rr < 4; rr++) {
        const int r = fr + rr * 16;
        float4 v = *(const float4*)&x[(size_t)(n0 + r) * D + c0 + fc * 4];
        tile[r][fc * 4 + 0] = v.x;
        tile[r][fc * 4 + 1] = v.y;
        tile[r][fc * 4 + 2] = v.z;
        tile[r][fc * 4 + 3] = v.w;
    }
    __syncthreads();

    // Transposed write: thread owns column (c0+c), n-range seg*16..+16
    const int c   = t >> 2;  // 0..63
    const int seg = t & 3;   // 0..3
    float ssq = 0.f;
    __align__(16) __nv_bfloat16 vals[16];
    #pragma unroll
    for (int i = 0; i < 16; i++) {
        const float v = tile[seg * 16 + i][c];
        ssq += v * v;                       // fp32 BEFORE bf16 rounding
        vals[i] = __float2bfloat16(v);
    }
    __nv_bfloat16* dst = &g_Xt[(size_t)(c0 + c) * NTOK + n0 + seg * 16];
    *(uint4*)(dst + 0) = *(uint4*)&vals[0];
    *(uint4*)(dst + 8) = *(uint4*)&vals[8];

    // reduce the 4 seg-lanes (adjacent in warp) -> 64-row partial
    ssq += __shfl_xor_sync(0xffffffffu, ssq, 1);
    ssq += __shfl_xor_sync(0xffffffffu, ssq, 2);
    if (seg == 0) g_colsq[(size_t)blockIdx.x * D + c0 + c] = ssq;
}

// ---------------------------------------------------------------------------
// Kernel 2: split-K SYRK, C_part[s] = X_s^T X_s via mma.sync bf16 m16n8k16
// grid = (36, 8), block = 256 (8 warps, 2x4 warp tiling of 128x128)
// ---------------------------------------------------------------------------
__global__ __launch_bounds__(256, 2) void gemm_kernel() {
    __shared__ __nv_bfloat16 smA[2][128][KPAD];
    __shared__ __nv_bfloat16 smB[2][128][KPAD];

    const int tid  = threadIdx.x;
    const int mi   = blockIdx.x / NTILE;
    const int ni   = blockIdx.x % NTILE;
    const int m0   = mi * 128;
    const int n0   = ni * 128;
    const int s    = blockIdx.y;
    const size_t kbase = (size_t)s * KSPLIT;

    const int warp = tid >> 5, lane = tid & 31;
    const int wm = warp >> 2;         // 0..1  (64 rows each)
    const int wn = warp & 3;          // 0..3  (32 cols each)
    const int g  = lane >> 2;         // 0..7
    const int tg = lane & 3;          // 0..3

    float acc[4][4][4];
    #pragma unroll
    for (int a = 0; a < 4; a++)
        #pragma unroll
        for (int b = 0; b < 4; b++)
            #pragma unroll
            for (int c = 0; c < 4; c++) acc[a][b][c] = 0.f;

    // loader mapping: 512 uint4 per tile pair, 256 threads x 2
    const int lc = tid >> 2;          // 0..63
    const int lk = (tid & 3) * 8;     // 0,8,16,24 (bf16 elements along k)

    uint4 rA0, rA1, rB0, rB1;

    // prologue: iter 0
    {
        const size_t kb = kbase + lk;
        rA0 = *(const uint4*)&g_Xt[(size_t)(m0 + lc)      * NTOK + kb];
        rA1 = *(const uint4*)&g_Xt[(size_t)(m0 + lc + 64) * NTOK + kb];
        rB0 = *(const uint4*)&g_Xt[(size_t)(n0 + lc)      * NTOK + kb];
        rB1 = *(const uint4*)&g_Xt[(size_t)(n0 + lc + 64) * NTOK + kb];
        *(uint2*)&smA[0][lc][lk]          = make_uint2(rA0.x, rA0.y);
        *(uint2*)&smA[0][lc][lk + 4]      = make_uint2(rA0.z, rA0.w);
        *(uint2*)&smA[0][lc + 64][lk]     = make_uint2(rA1.x, rA1.y);
        *(uint2*)&smA[0][lc + 64][lk + 4] = make_uint2(rA1.z, rA1.w);
        *(uint2*)&smB[0][lc][lk]          = make_uint2(rB0.x, rB0.y);
        *(uint2*)&smB[0][lc][lk + 4]      = make_uint2(rB0.z, rB0.w);
        *(uint2*)&smB[0][lc + 64][lk]     = make_uint2(rB1.x, rB1.y);
        *(uint2*)&smB[0][lc + 64][lk + 4] = make_uint2(rB1.z, rB1.w);
    }
    __syncthreads();

    int p = 0;
    for (int it = 0; it < NIT; ++it) {
        // issue next tile's global loads (latency hidden under compute)
        if (it + 1 < NIT) {
            const size_t kb = kbase + (size_t)(it + 1) * KT + lk;
            rA0 = *(const uint4*)&g_Xt[(size_t)(m0 + lc)      * NTOK + kb];
            rA1 = *(const uint4*)&g_Xt[(size_t)(m0 + lc + 64) * NTOK + kb];
            rB0 = *(const uint4*)&g_Xt[(size_t)(n0 + lc)      * NTOK + kb];
            rB1 = *(const uint4*)&g_Xt[(size_t)(n0 + lc + 64) * NTOK + kb];
        }

        // compute on buffer p
        #pragma unroll
        for (int kk = 0; kk < KT; kk += 16) {
            uint32_t a[4][4], b[4][2];
            #pragma unroll
            for (int mf = 0; mf < 4; mf++) {
                const __nv_bfloat16* pa = &smA[p][wm * 64 + mf * 16 + g][kk + 2 * tg];
                a[mf][0] = *(const uint32_t*)(pa);
                a[mf][1] = *(const uint32_t*)(pa + 8 * KPAD);
                a[mf][2] = *(const uint32_t*)(pa + 8);
                a[mf][3] = *(const uint32_t*)(pa + 8 * KPAD + 8);
            }
            #pragma unroll
            for (int nf = 0; nf < 4; nf++) {
                const __nv_bfloat16* pb = &smB[p][wn * 32 + nf * 8 + g][kk + 2 * tg];
                b[nf][0] = *(const uint32_t*)(pb);
                b[nf][1] = *(const uint32_t*)(pb + 8);
            }
            #pragma unroll
            for (int mf = 0; mf < 4; mf++)
                #pragma unroll
                for (int nf = 0; nf < 4; nf++) {
                    asm volatile(
                        "mma.sync.aligned.m16n8k16.row.col.f32.bf16.bf16.f32 "
                        "{%0,%1,%2,%3}, {%4,%5,%6,%7}, {%8,%9}, {%0,%1,%2,%3};\n"
                        : "+f"(acc[mf][nf][0]), "+f"(acc[mf][nf][1]),
                          "+f"(acc[mf][nf][2]), "+f"(acc[mf][nf][3])
                        : "r"(a[mf][0]), "r"(a[mf][1]), "r"(a[mf][2]), "r"(a[mf][3]),
                          "r"(b[nf][0]), "r"(b[nf][1]));
                }
        }

        if (it + 1 < NIT) {
            const int np = p ^ 1;
            *(uint2*)&smA[np][lc][lk]          = make_uint2(rA0.x, rA0.y);
            *(uint2*)&smA[np][lc][lk + 4]      = make_uint2(rA0.z, rA0.w);
            *(uint2*)&smA[np][lc + 64][lk]     = make_uint2(rA1.x, rA1.y);
            *(uint2*)&smA[np][lc + 64][lk + 4] = make_uint2(rA1.z, rA1.w);
            *(uint2*)&smB[np][lc][lk]          = make_uint2(rB0.x, rB0.y);
            *(uint2*)&smB[np][lc][lk + 4]      = make_uint2(rB0.z, rB0.w);
            *(uint2*)&smB[np][lc + 64][lk]     = make_uint2(rB1.x, rB1.y);
            *(uint2*)&smB[np][lc + 64][lk + 4] = make_uint2(rB1.z, rB1.w);
            __syncthreads();
            p = np;
        }
    }

    // epilogue: write partial tile
    float* outp = &g_part[(size_t)s * D * D];
    #pragma unroll
    for (int mf = 0; mf < 4; mf++) {
        #pragma unroll
        for (int nf = 0; nf < 4; nf++) {
            const int row = m0 + wm * 64 + mf * 16 + g;
            const int col = n0 + wn * 32 + nf * 8 + 2 * tg;
            *(float2*)&outp[(size_t)row * D + col]       = make_float2(acc[mf][nf][0], acc[mf][nf][1]);
            *(float2*)&outp[(size_t)(row + 8) * D + col] = make_float2(acc[mf][nf][2], acc[mf][nf][3]);
        }
    }
}

// ---------------------------------------------------------------------------
// Kernel 3: reduce splits, scale, subtract; diagonal from exact fp32 sum-sq
// ---------------------------------------------------------------------------
__global__ __launch_bounds__(256) void final_kernel(float* __restrict__ out) {
    const int idx = blockIdx.x * 256 + threadIdx.x;
    if (idx >= D * D) return;
    const int i = idx / D;
    const int j = idx % D;
    const float inv_n = 1.0f / (float)NTOK;
    float v;
    if (i == j) {
        float ms = 0.f;
        for (int b = 0; b < NBLK; b++) ms += g_colsq[(size_t)b * D + i];
        v = 0.5f * (ms * inv_n) - 0.5f;
    } else {
        float ssum = 0.f;
        #pragma unroll
        for (int sp = 0; sp < SPLIT; sp++) ssum += g_part[(size_t)sp * D * D + idx];
        v = 0.5f * (ssum * inv_n) - 0.5f;
    }
    out[idx] = v;
}

// ---------------------------------------------------------------------------
extern "C" void kernel_launch(void* const* d_in, const int* in_sizes, int n_in,
                              void* d_out, int out_size) {
    const float* x = (const float*)d_in[0];
    float* out = (float*)d_out;
    (void)in_sizes; (void)n_in; (void)out_size;

    convert_kernel<<<dim3(NTOK / 64, D / 64), 256>>>(x);
    gemm_kernel<<<dim3(NTILE * NTILE, SPLIT), 256>>>();
    final_kernel<<<(D * D + 255) / 256, 256>>>(out);
}

// round 2
// speedup vs baseline: 1.2421x; 1.2421x over previous
#include <cuda_runtime.h>
#include <cuda_bf16.h>
#include <cstdint>

#define D      768
#define NTOK   16384          // 8 * 2048
#define NSPLIT 14             // 21 tiles * 14 = 294 CTAs ~= one full wave @ occ 2
#define KT     32
#define KPAD   40
#define KTILES (NTOK / KT)    // 512
#define NTILE  6              // 768 / 128
#define NPAIRS (NTILE * (NTILE + 1) / 2)  // 21 upper-triangular tile pairs
#define NBLK   (NTOK / 64)    // 256

// Scratch (allocation-free rule: __device__ globals)
__device__ __nv_bfloat16 g_Xt[(size_t)D * NTOK];          // X transposed, bf16
__device__ float         g_part[(size_t)NSPLIT * D * D];  // split-K partials
__device__ float         g_colsq[(size_t)NBLK * D];       // fp32 sum(x^2) partials

// ---------------------------------------------------------------------------
// Kernel 1: fp32 [N,768] -> bf16 transposed [768,N], fused fp32 column sum-sq
// ---------------------------------------------------------------------------
__global__ __launch_bounds__(256) void convert_kernel(const float* __restrict__ x) {
    __shared__ float tile[64][65];
    const int n0 = blockIdx.x * 64;
    const int c0 = blockIdx.y * 64;
    const int t  = threadIdx.x;

    const int fr = t >> 4;
    const int fc = t & 15;
    #pragma unroll
    for (int rr = 0; rr < 4; rr++) {
        const int r = fr + rr * 16;
        float4 v = *(const float4*)&x[(size_t)(n0 + r) * D + c0 + fc * 4];
        tile[r][fc * 4 + 0] = v.x;
        tile[r][fc * 4 + 1] = v.y;
        tile[r][fc * 4 + 2] = v.z;
        tile[r][fc * 4 + 3] = v.w;
    }
    __syncthreads();

    const int c   = t >> 2;
    const int seg = t & 3;
    float ssq = 0.f;
    __align__(16) __nv_bfloat16 vals[16];
    #pragma unroll
    for (int i = 0; i < 16; i++) {
        const float v = tile[seg * 16 + i][c];
        ssq += v * v;
        vals[i] = __float2bfloat16(v);
    }
    __nv_bfloat16* dst = &g_Xt[(size_t)(c0 + c) * NTOK + n0 + seg * 16];
    *(uint4*)(dst + 0) = *(uint4*)&vals[0];
    *(uint4*)(dst + 8) = *(uint4*)&vals[8];

    ssq += __shfl_xor_sync(0xffffffffu, ssq, 1);
    ssq += __shfl_xor_sync(0xffffffffu, ssq, 2);
    if (seg == 0) g_colsq[(size_t)blockIdx.x * D + c0 + c] = ssq;
}

// ---------------------------------------------------------------------------
// Kernel 2: split-K SYRK on upper-triangular tile pairs, ldmatrix + mma.sync
// grid = (21, 14), block = 256 (8 warps, 2x4 warp tiling of 128x128)
// ---------------------------------------------------------------------------
__global__ __launch_bounds__(256, 2) void gemm_kernel() {
    __shared__ __nv_bfloat16 smA[2][128][KPAD];
    __shared__ __nv_bfloat16 smB[2][128][KPAD];

    const int tid = threadIdx.x;

    // map blockIdx.x -> upper-triangular (mi, ni), mi <= ni
    int trem = blockIdx.x, mi = 0;
    while (trem >= NTILE - mi) { trem -= NTILE - mi; mi++; }
    const int ni = mi + trem;
    const int m0 = mi * 128;
    const int n0 = ni * 128;

    // uneven split-K: k-tile range for this split
    const int s   = blockIdx.y;
    const int kt0 = (s * KTILES) / NSPLIT;
    const int kt1 = ((s + 1) * KTILES) / NSPLIT;
    const int nit = kt1 - kt0;
    const size_t kbase = (size_t)kt0 * KT;

    const int warp = tid >> 5, lane = tid & 31;
    const int wm = warp >> 2;   // 0..1  (64 rows)
    const int wn = warp & 3;    // 0..3  (32 cols)
    const int g  = lane >> 3;   // unused in frag math now
    (void)g;

    float acc[4][4][4];
    #pragma unroll
    for (int a = 0; a < 4; a++)
        #pragma unroll
        for (int b = 0; b < 4; b++)
            #pragma unroll
            for (int c = 0; c < 4; c++) acc[a][b][c] = 0.f;

    // ldmatrix per-lane byte offsets (relative to buffer base), constant over kk
    // A (x4, m16k16 per mf): lanes 0-15 -> rows 0-15 @k, lanes 16-31 -> rows 0-15 @k+8
    uint32_t offA[4];
    {
        const int r  = lane & 15;
        const int kx = (lane >> 4) << 3;
        #pragma unroll
        for (int mf = 0; mf < 4; mf++)
            offA[mf] = ((wm * 64 + mf * 16 + r) * KPAD + kx) * 2;
    }
    // B (x4 covering two n8 tiles): lanes 0-7 rowsE@k, 8-15 rowsE@k+8,
    //                               16-23 rowsO@k, 24-31 rowsO@k+8
    uint32_t offB[2];
    {
        const int r  = lane & 7;
        const int ko = ((lane >> 3) & 1) << 3;
        const int po = (lane >> 4) & 1;
        #pragma unroll
        for (int p2 = 0; p2 < 2; p2++)
            offB[p2] = ((wn * 32 + (2 * p2 + po) * 8 + r) * KPAD + ko) * 2;
    }
    const uint32_t baseA0 = (uint32_t)__cvta_generic_to_shared(&smA[0][0][0]);
    const uint32_t baseA1 = (uint32_t)__cvta_generic_to_shared(&smA[1][0][0]);
    const uint32_t baseB0 = (uint32_t)__cvta_generic_to_shared(&smB[0][0][0]);
    const uint32_t baseB1 = (uint32_t)__cvta_generic_to_shared(&smB[1][0][0]);

    // loader mapping: 256 threads, each carries 4 uint4 per stage
    const int lc = tid >> 2;
    const int lk = (tid & 3) * 8;

    uint4 rA0, rA1, rB0, rB1;

    // prologue
    {
        const size_t kb = kbase + lk;
        rA0 = *(const uint4*)&g_Xt[(size_t)(m0 + lc)      * NTOK + kb];
        rA1 = *(const uint4*)&g_Xt[(size_t)(m0 + lc + 64) * NTOK + kb];
        rB0 = *(const uint4*)&g_Xt[(size_t)(n0 + lc)      * NTOK + kb];
        rB1 = *(const uint4*)&g_Xt[(size_t)(n0 + lc + 64) * NTOK + kb];
        *(uint2*)&smA[0][lc][lk]          = make_uint2(rA0.x, rA0.y);
        *(uint2*)&smA[0][lc][lk + 4]      = make_uint2(rA0.z, rA0.w);
        *(uint2*)&smA[0][lc + 64][lk]     = make_uint2(rA1.x, rA1.y);
        *(uint2*)&smA[0][lc + 64][lk + 4] = make_uint2(rA1.z, rA1.w);
        *(uint2*)&smB[0][lc][lk]          = make_uint2(rB0.x, rB0.y);
        *(uint2*)&smB[0][lc][lk + 4]      = make_uint2(rB0.z, rB0.w);
        *(uint2*)&smB[0][lc + 64][lk]     = make_uint2(rB1.x, rB1.y);
        *(uint2*)&smB[0][lc + 64][lk + 4] = make_uint2(rB1.z, rB1.w);
    }
    __syncthreads();

    int p = 0;
    for (int it = 0; it < nit; ++it) {
        if (it + 1 < nit) {
            const size_t kb = kbase + (size_t)(it + 1) * KT + lk;
            rA0 = *(const uint4*)&g_Xt[(size_t)(m0 + lc)      * NTOK + kb];
            rA1 = *(const uint4*)&g_Xt[(size_t)(m0 + lc + 64) * NTOK + kb];
            rB0 = *(const uint4*)&g_Xt[(size_t)(n0 + lc)      * NTOK + kb];
            rB1 = *(const uint4*)&g_Xt[(size_t)(n0 + lc + 64) * NTOK + kb];
        }

        const uint32_t bA = p ? baseA1 : baseA0;
        const uint32_t bB = p ? baseB1 : baseB0;

        #pragma unroll
        for (int kk = 0; kk < KT; kk += 16) {
            uint32_t a[4][4], b[4][2];
            #pragma unroll
            for (int mf = 0; mf < 4; mf++) {
                asm volatile(
                    "ldmatrix.sync.aligned.m8n8.x4.shared.b16 {%0,%1,%2,%3}, [%4];\n"
                    : "=r"(a[mf][0]), "=r"(a[mf][1]), "=r"(a[mf][2]), "=r"(a[mf][3])
                    : "r"(bA + offA[mf] + kk * 2));
            }
            #pragma unroll
            for (int p2 = 0; p2 < 2; p2++) {
                asm volatile(
                    "ldmatrix.sync.aligned.m8n8.x4.shared.b16 {%0,%1,%2,%3}, [%4];\n"
                    : "=r"(b[2 * p2][0]), "=r"(b[2 * p2][1]),
                      "=r"(b[2 * p2 + 1][0]), "=r"(b[2 * p2 + 1][1])
                    : "r"(bB + offB[p2] + kk * 2));
            }
            #pragma unroll
            for (int mf = 0; mf < 4; mf++)
                #pragma unroll
                for (int nf = 0; nf < 4; nf++) {
                    asm volatile(
                        "mma.sync.aligned.m16n8k16.row.col.f32.bf16.bf16.f32 "
                        "{%0,%1,%2,%3}, {%4,%5,%6,%7}, {%8,%9}, {%0,%1,%2,%3};\n"
                        : "+f"(acc[mf][nf][0]), "+f"(acc[mf][nf][1]),
                          "+f"(acc[mf][nf][2]), "+f"(acc[mf][nf][3])
                        : "r"(a[mf][0]), "r"(a[mf][1]), "r"(a[mf][2]), "r"(a[mf][3]),
                          "r"(b[nf][0]), "r"(b[nf][1]));
                }
        }

        if (it + 1 < nit) {
            const int np = p ^ 1;
            __syncthreads();   // all warps done reading buffer np from 2 iters ago
            *(uint2*)&smA[np][lc][lk]          = make_uint2(rA0.x, rA0.y);
            *(uint2*)&smA[np][lc][lk + 4]      = make_uint2(rA0.z, rA0.w);
            *(uint2*)&smA[np][lc + 64][lk]     = make_uint2(rA1.x, rA1.y);
            *(uint2*)&smA[np][lc + 64][lk + 4] = make_uint2(rA1.z, rA1.w);
            *(uint2*)&smB[np][lc][lk]          = make_uint2(rB0.x, rB0.y);
            *(uint2*)&smB[np][lc][lk + 4]      = make_uint2(rB0.z, rB0.w);
            *(uint2*)&smB[np][lc + 64][lk]     = make_uint2(rB1.x, rB1.y);
            *(uint2*)&smB[np][lc + 64][lk + 4] = make_uint2(rB1.z, rB1.w);
            __syncthreads();
            p = np;
        }
    }

    // epilogue: write partial tile (upper-triangular position only)
    const int lg = lane >> 2, tg = lane & 3;
    float* outp = &g_part[(size_t)s * D * D];
    #pragma unroll
    for (int mf = 0; mf < 4; mf++) {
        #pragma unroll
        for (int nf = 0; nf < 4; nf++) {
            const int row = m0 + wm * 64 + mf * 16 + lg;
            const int col = n0 + wn * 32 + nf * 8 + 2 * tg;
            *(float2*)&outp[(size_t)row * D + col]       = make_float2(acc[mf][nf][0], acc[mf][nf][1]);
            *(float2*)&outp[(size_t)(row + 8) * D + col] = make_float2(acc[mf][nf][2], acc[mf][nf][3]);
        }
    }
}

// ---------------------------------------------------------------------------
// Kernel 3: reduce splits (mirroring lower triangle), scale, subtract;
// diagonal from exact fp32 sum-sq
// ---------------------------------------------------------------------------
__global__ __launch_bounds__(256) void final_kernel(float* __restrict__ out) {
    const int idx = blockIdx.x * 256 + threadIdx.x;
    if (idx >= D * D) return;
    const int i = idx / D;
    const int j = idx % D;
    const float inv_n = 1.0f / (float)NTOK;
    float v;
    if (i == j) {
        float ms = 0.f;
        for (int b = 0; b < NBLK; b++) ms += g_colsq[(size_t)b * D + i];
        v = 0.5f * (ms * inv_n) - 0.5f;
    } else {
        // only upper-triangular tiles were computed; mirror if needed
        const int src = ((i >> 7) <= (j >> 7)) ? (i * D + j) : (j * D + i);
        float ssum = 0.f;
        #pragma unroll
        for (int sp = 0; sp < NSPLIT; sp++) ssum += g_part[(size_t)sp * D * D + src];
        v = 0.5f * (ssum * inv_n) - 0.5f;
    }
    out[idx] = v;
}

// ---------------------------------------------------------------------------
extern "C" void kernel_launch(void* const* d_in, const int* in_sizes, int n_in,
                              void* d_out, int out_size) {
    const float* x = (const float*)d_in[0];
    float* out = (float*)d_out;
    (void)in_sizes; (void)n_in; (void)out_size;

    convert_kernel<<<dim3(NTOK / 64, D / 64), 256>>>(x);
    gemm_kernel<<<dim3(NPAIRS, NSPLIT), 256>>>();
    final_kernel<<<(D * D + 255) / 256, 256>>>(out);
}